// round 2
// baseline (speedup 1.0000x reference)
#include <cuda_runtime.h>
#include <cstdint>
#include <cmath>

#define NODES 20000
#define BATCH 8
#define DEG 32
#define NB 8

// Scratch (allocation-free rule: __device__ globals)
__device__ float4 g_pos4[BATCH * NODES];
__device__ int    g_idx[NODES * DEG];

__device__ __forceinline__ float fsin(float x) {
    float r; asm("sin.approx.ftz.f32 %0, %1;" : "=f"(r) : "f"(x)); return r;
}
__device__ __forceinline__ float fex2(float x) {
    float r; asm("ex2.approx.ftz.f32 %0, %1;" : "=f"(r) : "f"(x)); return r;
}
__device__ __forceinline__ unsigned long long pk(float a, float b) {
    unsigned long long r; asm("mov.b64 %0, {%1, %2};" : "=l"(r) : "f"(a), "f"(b)); return r;
}
__device__ __forceinline__ void upk(unsigned long long v, float& a, float& b) {
    asm("mov.b64 {%0, %1}, %2;" : "=f"(a), "=f"(b) : "l"(v));
}
__device__ __forceinline__ unsigned long long ffma2(unsigned long long a, unsigned long long b, unsigned long long c) {
    unsigned long long r; asm("fma.rn.f32x2 %0, %1, %2, %3;" : "=l"(r) : "l"(a), "l"(b), "l"(c)); return r;
}
__device__ __forceinline__ unsigned long long fmul2(unsigned long long a, unsigned long long b) {
    unsigned long long r; asm("mul.rn.f32x2 %0, %1, %2;" : "=l"(r) : "l"(a), "l"(b)); return r;
}

// Repack pos -> float4 (1 LDG.128 per gather in main kernel) and
// nbr_idx -> int32. Robust to nbr_idx arriving as int64 OR int32 (JAX
// x64-default ambiguity): if the odd 32-bit words 1..63 are all zero it is
// int64 (high halves of small non-negative values); int32 random indices make
// that event probability ~ (1/20000)^32.
__global__ void prep_kernel(const float* __restrict__ pos, const void* __restrict__ nbr) {
    int t = blockIdx.x * blockDim.x + threadIdx.x;
    const int* w = (const int*)nbr;
    bool is64 = true;
#pragma unroll
    for (int k = 1; k < 64; k += 2) is64 &= (w[k] == 0);
    if (t < NODES * DEG) {
        int v;
        if (is64) v = (int)((const long long*)nbr)[t];
        else      v = w[t];
        g_idx[t] = v;
    }
    if (t < BATCH * NODES) {
        g_pos4[t] = make_float4(pos[3 * t + 0], pos[3 * t + 1], pos[3 * t + 2], 0.f);
    }
}

__global__ void __launch_bounds__(128, 4) embed_kernel(
    const float* __restrict__ box, float* __restrict__ out,
    float K2, float T2, float E2, float S2)
{
    int i = blockIdx.x * blockDim.x + threadIdx.x;
    int b = blockIdx.y;
    if (i >= NODES) return;

    const float INV2PI = 0.15915494309189535f;
    float ab0 = box[0] * INV2PI, ab1 = box[1] * INV2PI, ab2 = box[2] * INV2PI;
    float ia0 = 1.0f / ab0, ia1 = 1.0f / ab1, ia2 = 1.0f / ab2;

    const float4* __restrict__ pb = g_pos4 + b * NODES;
    float4 own = pb[i];
    const int4* __restrict__ row = (const int4*)(g_idx + i * DEG);

    const float OFF = 64.0f;                        // exponent bias vs underflow
    const float SC  = 5.421010862427522e-20f;       // 2^-64
    const unsigned long long S2p = pk(S2, S2);

    unsigned long long accA[NB], accB[NB];          // (yv0,yv1), (yv2,y)
#pragma unroll
    for (int n = 0; n < NB; n++) { accA[n] = 0ull; accB[n] = 0ull; }

#pragma unroll 2
    for (int c = 0; c < DEG / 4; c++) {
        int4 q = row[c];
        int js[4] = {q.x, q.y, q.z, q.w};
#pragma unroll
        for (int u = 0; u < 4; u++) {
            float4 np = pb[js[u]];
            float e0 = ab0 * fsin((np.x - own.x) * ia0);
            float e1 = ab1 * fsin((np.y - own.y) * ia1);
            float e2 = ab2 * fsin((np.z - own.z) * ia2);
            float r  = fmaf(e0, e0, fmaf(e1, e1, e2 * e2));
            // x_n = 2^(OFF - K2*(r - n*Delta)^2) via 2-exp recurrence
            float x = fex2(fmaf(-K2 * r, r, OFF));
            float m = fex2(fmaf(T2, r, -E2));
            unsigned long long e01 = pk(e0 * SC, e1 * SC);
            unsigned long long e2o = pk(e2 * SC, SC);
            unsigned long long xx = pk(x, x);
            unsigned long long mm = pk(m, m);
#pragma unroll
            for (int n = 0; n < NB; n++) {
                accA[n] = ffma2(xx, e01, accA[n]);
                accB[n] = ffma2(xx, e2o, accB[n]);
                if (n < NB - 1) {
                    xx = fmul2(xx, mm);
                    mm = fmul2(mm, S2p);
                }
            }
        }
    }

    long bn = (long)b * NODES + i;
    float yv[3 * NB], yy[NB];
#pragma unroll
    for (int n = 0; n < NB; n++) {
        upk(accA[n], yv[3 * n + 0], yv[3 * n + 1]);
        upk(accB[n], yv[3 * n + 2], yy[n]);
    }
    // y: (B, N, 8) then yv: (B, N, 8, 3) concatenated
    float4* yo = (float4*)(out + bn * NB);
    yo[0] = make_float4(yy[0], yy[1], yy[2], yy[3]);
    yo[1] = make_float4(yy[4], yy[5], yy[6], yy[7]);
    float4* vo = (float4*)(out + (long)BATCH * NODES * NB + bn * (3 * NB));
#pragma unroll
    for (int k = 0; k < 6; k++)
        vo[k] = make_float4(yv[4 * k + 0], yv[4 * k + 1], yv[4 * k + 2], yv[4 * k + 3]);
}

extern "C" void kernel_launch(void* const* d_in, const int* in_sizes, int n_in,
                              void* d_out, int out_size)
{
    const float* pos = (const float*)d_in[0];
    const float* box = (const float*)d_in[1];
    const void*  nbr = d_in[2];
    float* out = (float*)d_out;

    // RBF constants: mu_n = n*(2.5/7), sigma = 2.5/8 -> k = 0.5/sigma^2 = 5.12
    // exp2 domain: x_n = 2^(-K2 (r - n*Delta)^2)
    const double log2e = 1.4426950408889634074;
    const double kq    = 5.12;
    const double delta = 2.5 / 7.0;
    float K2 = (float)(kq * log2e);                          // 7.3865986...
    float T2 = (float)(2.0 * kq * delta * log2e);            // 5.2761419...
    float E2 = (float)(kq * delta * delta * log2e);          // 0.9421682...
    float S2 = (float)exp2(-2.0 * kq * delta * delta * log2e);

    int total = NODES * DEG;  // 640000 >= BATCH*NODES
    prep_kernel<<<(total + 255) / 256, 256>>>(pos, nbr);

    dim3 grid((NODES + 127) / 128, BATCH);
    embed_kernel<<<grid, 128>>>(box, out, K2, T2, E2, S2);
}

// round 3
// speedup vs baseline: 1.2089x; 1.2089x over previous
#include <cuda_runtime.h>
#include <cstdint>
#include <cmath>

#define NODES 20000
#define BATCH 8
#define DEG 32
#define NB 8
#define NPB 16                 // nodes per block (x 8 batches = 128 threads)
#define PITCH 33

// Scratch (allocation-free rule: __device__ globals)
__device__ float4 g_pos_t[NODES * BATCH];   // [node][batch] transposed
__device__ int    g_idx[NODES * DEG];

__device__ __forceinline__ float fsin(float x) {
    float r; asm("sin.approx.ftz.f32 %0, %1;" : "=f"(r) : "f"(x)); return r;
}
__device__ __forceinline__ float fex2(float x) {
    float r; asm("ex2.approx.ftz.f32 %0, %1;" : "=f"(r) : "f"(x)); return r;
}
__device__ __forceinline__ unsigned long long pk(float a, float b) {
    unsigned long long r; asm("mov.b64 %0, {%1, %2};" : "=l"(r) : "f"(a), "f"(b)); return r;
}
__device__ __forceinline__ void upk(unsigned long long v, float& a, float& b) {
    asm("mov.b64 {%0, %1}, %2;" : "=f"(a), "=f"(b) : "l"(v));
}
__device__ __forceinline__ unsigned long long ffma2(unsigned long long a, unsigned long long b, unsigned long long c) {
    unsigned long long r; asm("fma.rn.f32x2 %0, %1, %2, %3;" : "=l"(r) : "l"(a), "l"(b), "l"(c)); return r;
}
__device__ __forceinline__ unsigned long long fmul2(unsigned long long a, unsigned long long b) {
    unsigned long long r; asm("mul.rn.f32x2 %0, %1, %2;" : "=l"(r) : "l"(a), "l"(b)); return r;
}

// Prep: idx int64->int32 (with dtype autodetect) and pos -> transposed float4
// table pos_t[node][batch] so that the 8 batch-lanes of one node gather a
// single 128B line in the main kernel.
__global__ void prep_kernel(const float* __restrict__ pos, const void* __restrict__ nbr) {
    int t = blockIdx.x * blockDim.x + threadIdx.x;
    const int* w = (const int*)nbr;
    bool is64 = true;
#pragma unroll
    for (int k = 1; k < 64; k += 2) is64 &= (w[k] == 0);
    if (t < NODES * DEG) {
        int v;
        if (is64) v = (int)((const long long*)nbr)[t];
        else      v = w[t];
        g_idx[t] = v;
    }
    if (t < BATCH * NODES) {
        // t linear over (b, i): coalesced read of pos
        int b = t / NODES, i = t - b * NODES;
        g_pos_t[i * BATCH + b] =
            make_float4(pos[3 * t + 0], pos[3 * t + 1], pos[3 * t + 2], 0.f);
    }
}

__global__ void __launch_bounds__(128, 5) embed_kernel(
    const float* __restrict__ box, float* __restrict__ out,
    float K2, float T2, float E2, float S2)
{
    __shared__ int   sidx[NPB * DEG];          // 512 ints
    __shared__ float sm[128 * PITCH];          // staging: 16.5KB

    int tid = threadIdx.x;
    int b = tid & 7;           // batch lane
    int s = tid >> 3;          // node within block
    int ibase = blockIdx.x * NPB;
    int i = ibase + s;

    // neighbor rows for this block's 16 nodes: contiguous chunk
#pragma unroll
    for (int k = tid; k < NPB * DEG; k += 128)
        sidx[k] = g_idx[ibase * DEG + k];
    __syncthreads();

    const float INV2PI = 0.15915494309189535f;
    float ab0 = box[0] * INV2PI, ab1 = box[1] * INV2PI, ab2 = box[2] * INV2PI;
    float ia0 = 1.0f / ab0, ia1 = 1.0f / ab1, ia2 = 1.0f / ab2;

    const float4* __restrict__ pt = g_pos_t;
    float4 own = pt[i * BATCH + b];

    const float OFF = 64.0f;                        // exponent bias vs underflow
    const float SC  = 5.421010862427522e-20f;       // 2^-64
    const unsigned long long S2p = pk(S2, S2);

    unsigned long long accA[NB], accB[NB];          // (yv0,yv1), (yv2,y)
#pragma unroll
    for (int n = 0; n < NB; n++) { accA[n] = 0ull; accB[n] = 0ull; }

#pragma unroll 4
    for (int c = 0; c < DEG; c++) {
        int j = sidx[s * DEG + c];                  // broadcast within 8-lane group
        float4 np = pt[j * BATCH + b];              // 8 lanes -> one 128B line
        float e0 = ab0 * fsin((np.x - own.x) * ia0);
        float e1 = ab1 * fsin((np.y - own.y) * ia1);
        float e2 = ab2 * fsin((np.z - own.z) * ia2);
        float r  = fmaf(e0, e0, fmaf(e1, e1, e2 * e2));
        // x_n = 2^(OFF - K2*(r - n*Delta)^2) via 2-exp recurrence
        float x = fex2(fmaf(-K2 * r, r, OFF));
        float m = fex2(fmaf(T2, r, -E2));
        unsigned long long e01 = pk(e0 * SC, e1 * SC);
        unsigned long long e2o = pk(e2 * SC, SC);
        unsigned long long xx = pk(x, x);
        unsigned long long mm = pk(m, m);
#pragma unroll
        for (int n = 0; n < NB; n++) {
            accA[n] = ffma2(xx, e01, accA[n]);
            accB[n] = ffma2(xx, e2o, accB[n]);
            if (n < NB - 1) {
                xx = fmul2(xx, mm);
                mm = fmul2(mm, S2p);
            }
        }
    }

    // stage: row tid = (s,b); cols 0..7 = y[n], 8..31 = yv[n*3+d]
#pragma unroll
    for (int n = 0; n < NB; n++) {
        float a0, a1, a2, yv;
        upk(accA[n], a0, a1);
        upk(accB[n], a2, yv);
        sm[tid * PITCH + n] = yv;
        sm[tid * PITCH + 8 + 3 * n + 0] = a0;
        sm[tid * PITCH + 8 + 3 * n + 1] = a1;
        sm[tid * PITCH + 8 + 3 * n + 2] = a2;
    }
    __syncthreads();

    // coalesced write-out, batch-major output
    // y: (B, N, 8)
    {
        int s2 = tid >> 3, k = tid & 7;
#pragma unroll
        for (int bb = 0; bb < BATCH; bb++) {
            float v = sm[(s2 * 8 + bb) * PITCH + k];
            out[((long)bb * NODES + ibase + s2) * NB + k] = v;
        }
    }
    // yv: (B, N, 8, 3) after y
    {
        float* yvo = out + (long)BATCH * NODES * NB;
#pragma unroll
        for (int bb = 0; bb < BATCH; bb++) {
#pragma unroll
            for (int rep = 0; rep < 3; rep++) {
                int f = rep * 128 + tid;            // 0..383 within this batch chunk
                int s2 = f / 24, m = f - s2 * 24;
                float v = sm[(s2 * 8 + bb) * PITCH + 8 + m];
                yvo[((long)bb * NODES + ibase) * 24 + f] = v;
            }
        }
    }
}

extern "C" void kernel_launch(void* const* d_in, const int* in_sizes, int n_in,
                              void* d_out, int out_size)
{
    const float* pos = (const float*)d_in[0];
    const float* box = (const float*)d_in[1];
    const void*  nbr = d_in[2];
    float* out = (float*)d_out;

    // RBF constants: mu_n = n*(2.5/7), sigma = 2.5/8 -> k = 0.5/sigma^2 = 5.12
    // exp2 domain: x_n = 2^(-K2 (r - n*Delta)^2)
    const double log2e = 1.4426950408889634074;
    const double kq    = 5.12;
    const double delta = 2.5 / 7.0;
    float K2 = (float)(kq * log2e);
    float T2 = (float)(2.0 * kq * delta * log2e);
    float E2 = (float)(kq * delta * delta * log2e);
    float S2 = (float)exp2(-2.0 * kq * delta * delta * log2e);

    int total = NODES * DEG;  // 640000 >= BATCH*NODES
    prep_kernel<<<(total + 255) / 256, 256>>>(pos, nbr);

    embed_kernel<<<NODES / NPB, 128>>>(box, out, K2, T2, E2, S2);
}

// round 4
// speedup vs baseline: 1.3467x; 1.1139x over previous
#include <cuda_runtime.h>
#include <cstdint>
#include <cmath>

#define NODES 20000
#define BATCH 8
#define DEG 32
#define NB 8
#define NPB 8                  // nodes per block (x 8 batches = 64 threads)
#define PITCH 33

// Scratch (allocation-free rule: __device__ globals)
__device__ float4 g_pos_t[NODES * BATCH];   // [node][batch], pre-scaled by 2pi/box
__device__ int    g_idx[NODES * DEG];

__device__ __forceinline__ float fsin(float x) {
    float r; asm("sin.approx.ftz.f32 %0, %1;" : "=f"(r) : "f"(x)); return r;
}
__device__ __forceinline__ float fex2(float x) {
    float r; asm("ex2.approx.ftz.f32 %0, %1;" : "=f"(r) : "f"(x)); return r;
}
__device__ __forceinline__ unsigned long long pk(float a, float b) {
    unsigned long long r; asm("mov.b64 %0, {%1, %2};" : "=l"(r) : "f"(a), "f"(b)); return r;
}
__device__ __forceinline__ void upk(unsigned long long v, float& a, float& b) {
    asm("mov.b64 {%0, %1}, %2;" : "=f"(a), "=f"(b) : "l"(v));
}
__device__ __forceinline__ unsigned long long ffma2(unsigned long long a, unsigned long long b, unsigned long long c) {
    unsigned long long r; asm("fma.rn.f32x2 %0, %1, %2, %3;" : "=l"(r) : "l"(a), "l"(b), "l"(c)); return r;
}
__device__ __forceinline__ unsigned long long fmul2(unsigned long long a, unsigned long long b) {
    unsigned long long r; asm("mul.rn.f32x2 %0, %1, %2;" : "=l"(r) : "l"(a), "l"(b)); return r;
}
__device__ __forceinline__ unsigned long long fadd2(unsigned long long a, unsigned long long b) {
    unsigned long long r; asm("add.rn.f32x2 %0, %1, %2;" : "=l"(r) : "l"(a), "l"(b)); return r;
}

// Prep: idx int64->int32 (dtype autodetect) and pos -> transposed float4
// table pos_t[node][batch], PRE-SCALED by 2pi/box so the edge loop skips the
// ia multiply. 8 batch-lanes of one node gather a single 128B line.
__global__ void prep_kernel(const float* __restrict__ pos,
                            const float* __restrict__ box,
                            const void* __restrict__ nbr) {
    int t = blockIdx.x * blockDim.x + threadIdx.x;
    const int* w = (const int*)nbr;
    bool is64 = true;
#pragma unroll
    for (int k = 1; k < 64; k += 2) is64 &= (w[k] == 0);
    if (t < NODES * DEG) {
        int v;
        if (is64) v = (int)((const long long*)nbr)[t];
        else      v = w[t];
        g_idx[t] = v;
    }
    if (t < BATCH * NODES) {
        const float TWOPI = 6.283185307179586f;
        float ia0 = TWOPI / box[0], ia1 = TWOPI / box[1], ia2 = TWOPI / box[2];
        int b = t / NODES, i = t - b * NODES;       // coalesced read of pos
        g_pos_t[i * BATCH + b] = make_float4(pos[3 * t + 0] * ia0,
                                             pos[3 * t + 1] * ia1,
                                             pos[3 * t + 2] * ia2, 0.f);
    }
}

__global__ void __launch_bounds__(64, 12) embed_kernel(
    const float* __restrict__ box, float* __restrict__ out,
    float K2, float T2, float E2,
    float CS1, float CS2, float CS4lo)   // S2, S2^2, S2^4
{
    __shared__ int   sidx[NPB * DEG];          // 256 ints
    __shared__ float sm[64 * PITCH];           // staging 8.4KB

    int tid = threadIdx.x;
    int b = tid & 7;           // batch lane
    int s = tid >> 3;          // node within block
    int ibase = blockIdx.x * NPB;
    int i = ibase + s;

    // neighbor rows for this block's 8 nodes: one int4 per thread
    ((int4*)sidx)[tid] = ((const int4*)(g_idx + ibase * DEG))[tid];
    __syncthreads();

    const float INV2PI = 0.15915494309189535f;
    float ab0 = box[0] * INV2PI, ab1 = box[1] * INV2PI, ab2 = box[2] * INV2PI;

    const float4* __restrict__ pt = g_pos_t;
    float4 own = pt[i * BATCH + b];

    const float OFF = 64.0f;                       // exponent bias vs underflow
    const unsigned long long S4p = pk(CS4lo, CS4lo);

    // accumulators: 4 basis-pairs x {y, e0, e1, e2}
    unsigned long long aY[4], a0[4], a1[4], a2[4];
#pragma unroll
    for (int k = 0; k < 4; k++) { aY[k] = 0ull; a0[k] = 0ull; a1[k] = 0ull; a2[k] = 0ull; }

#pragma unroll 2
    for (int c = 0; c < DEG; c++) {
        int j = sidx[s * DEG + c];                 // broadcast within 8-lane group
        float4 np = pt[j * BATCH + b];             // 8 lanes -> one 128B line
        float e0 = ab0 * fsin(np.x - own.x);
        float e1 = ab1 * fsin(np.y - own.y);
        float e2 = ab2 * fsin(np.z - own.z);
        float r  = fmaf(e0, e0, fmaf(e1, e1, e2 * e2));
        // x_n = 2^(OFF - K2*(r - n*Delta)^2); pairs (x_2k, x_2k+1) via
        // X_{k+1} = X_k * P_k,  P_k = (m^2 S2^{4k+1}, m^2 S2^{4k+3}),
        // P_{k+1} = P_k * S2^4. x0 = 2^(OFF-K2 r^2), m = 2^(T2 r - E2).
        float x0 = fex2(fmaf(-K2 * r, r, OFF));
        float m  = fex2(fmaf(T2, r, -E2));
        float m2 = m * m;
        float pA = m2 * CS1;
        float pB = pA * CS2;
        float x1 = x0 * m;
        unsigned long long X = pk(x0, x1);
        unsigned long long P = pk(pA, pB);
        unsigned long long E0 = pk(e0, e0);
        unsigned long long E1 = pk(e1, e1);
        unsigned long long E2p = pk(e2, e2);
#pragma unroll
        for (int k = 0; k < 4; k++) {
            aY[k] = fadd2(X, aY[k]);
            a0[k] = ffma2(X, E0, a0[k]);
            a1[k] = ffma2(X, E1, a1[k]);
            a2[k] = ffma2(X, E2p, a2[k]);
            if (k < 3) {
                X = fmul2(X, P);
                P = fmul2(P, S4p);
            }
        }
    }

    const float SC = 5.421010862427522e-20f;       // 2^-64 unbias
    // stage: row tid = (s,b); cols 0..7 = y[n], 8..31 = yv[n*3+d]
#pragma unroll
    for (int k = 0; k < 4; k++) {
        float ylo, yhi, v0lo, v0hi, v1lo, v1hi, v2lo, v2hi;
        upk(aY[k], ylo, yhi);
        upk(a0[k], v0lo, v0hi);
        upk(a1[k], v1lo, v1hi);
        upk(a2[k], v2lo, v2hi);
        int n0 = 2 * k, n1 = 2 * k + 1;
        sm[tid * PITCH + n0] = ylo * SC;
        sm[tid * PITCH + n1] = yhi * SC;
        sm[tid * PITCH + 8 + 3 * n0 + 0] = v0lo * SC;
        sm[tid * PITCH + 8 + 3 * n0 + 1] = v1lo * SC;
        sm[tid * PITCH + 8 + 3 * n0 + 2] = v2lo * SC;
        sm[tid * PITCH + 8 + 3 * n1 + 0] = v0hi * SC;
        sm[tid * PITCH + 8 + 3 * n1 + 1] = v1hi * SC;
        sm[tid * PITCH + 8 + 3 * n1 + 2] = v2hi * SC;
    }
    __syncthreads();

    // coalesced write-out, batch-major output
    // y: (B, N, 8) — 64 floats per (batch, block): exactly one per thread
    {
        int s2 = tid >> 3, k = tid & 7;
#pragma unroll
        for (int bb = 0; bb < BATCH; bb++) {
            float v = sm[(s2 * 8 + bb) * PITCH + k];
            out[((long)bb * NODES + ibase + s2) * NB + k] = v;
        }
    }
    // yv: (B, N, 8, 3) after y — 192 floats per (batch, block): 3 reps
    {
        float* yvo = out + (long)BATCH * NODES * NB;
#pragma unroll
        for (int bb = 0; bb < BATCH; bb++) {
#pragma unroll
            for (int rep = 0; rep < 3; rep++) {
                int f = rep * 64 + tid;            // 0..191 within this chunk
                int s2 = f / 24, mcol = f - s2 * 24;
                float v = sm[(s2 * 8 + bb) * PITCH + 8 + mcol];
                yvo[((long)bb * NODES + ibase) * 24 + f] = v;
            }
        }
    }
}

extern "C" void kernel_launch(void* const* d_in, const int* in_sizes, int n_in,
                              void* d_out, int out_size)
{
    const float* pos = (const float*)d_in[0];
    const float* box = (const float*)d_in[1];
    const void*  nbr = d_in[2];
    float* out = (float*)d_out;

    // RBF: mu_n = n*(2.5/7), sigma = 2.5/8 -> k = 0.5/sigma^2 = 5.12
    // exp2 domain: x_n = 2^(-K2 (r - n*Delta)^2)
    const double log2e = 1.4426950408889634074;
    const double kq    = 5.12;
    const double delta = 2.5 / 7.0;
    float K2 = (float)(kq * log2e);
    float T2 = (float)(2.0 * kq * delta * log2e);
    float E2 = (float)(kq * delta * delta * log2e);
    double l2S2 = -2.0 * kq * delta * delta * log2e;   // log2(S2)
    float CS1 = (float)exp2(l2S2);
    float CS2 = (float)exp2(2.0 * l2S2);
    float CS4 = (float)exp2(4.0 * l2S2);

    int total = NODES * DEG;  // 640000 >= BATCH*NODES
    prep_kernel<<<(total + 255) / 256, 256>>>(pos, box, nbr);

    embed_kernel<<<NODES / NPB, 64>>>(box, out, K2, T2, E2, CS1, CS2, CS4);
}